// round 11
// baseline (speedup 1.0000x reference)
#include <cuda_runtime.h>

// CreateOverlappingWindows: x (B=64, T=2000, C=26) fp32 ->
// out (B*T, 19*26), N_CONTEXT=9, zero-padded edges.
//
// Persistent single-wave kernel: exactly 592 = 148 SMs x 4 blocks of 512
// threads (regs<=40 -> 4 blocks/SM resident), grid-striding the flat
// output float4 space. Perfect load balance, zero wave transitions.
//
// Flat identity (global): output float fe -> grow = fe/494,
//   src = fe - grow*468 - 234   (global x index, batch offset included)
//   valid iff p = src - (grow/2000)*52000 in [0, 52000).
// float2 never crosses an x row or an output row (26, 494 both even).

#define B_DIM    64
#define T_DIM    2000
#define C_DIM    26
#define WINDOW   19
#define ROW_F    (WINDOW * C_DIM)             // 494
#define SLIDE    (ROW_F - C_DIM)              // 468
#define XROW_F   (T_DIM * C_DIM)              // 52000 floats per batch
#define TOTAL_F4 (B_DIM * T_DIM * ROW_F / 4)  // 15,808,000 float4
#define NTHREADS 512
#define NBLOCKS  592                           // 148 SMs * 4

__global__ __launch_bounds__(NTHREADS, 4) void overlap_windows_kernel(
    const float* __restrict__ x, float* __restrict__ out)
{
    const int stride = NBLOCKS * NTHREADS;     // 303,104
    int i4 = blockIdx.x * NTHREADS + threadIdx.x;

    for (; i4 < TOTAL_F4; i4 += stride) {
        const int fe = i4 * 4;                 // global float offset (<2^26)

        // first float2 half
        const int grow0 = fe / ROW_F;                      // mul-hi /494
        const int k0    = fe - grow0 * ROW_F;              // 0..492, even
        const int src0  = fe - grow0 * SLIDE - 234;
        const int b0    = grow0 / T_DIM;                   // mul-hi /2000
        const int p0    = src0 - b0 * XROW_F;

        // second half: next output row iff k0+2 >= 494
        const int grow1 = grow0 + ((k0 + 2 >= ROW_F) ? 1 : 0);
        const int src1  = (fe + 2) - grow1 * SLIDE - 234;
        const int b1    = grow1 / T_DIM;
        const int p1    = src1 - b1 * XROW_F;

        float2 a = make_float2(0.0f, 0.0f);
        float2 c = make_float2(0.0f, 0.0f);
        if ((unsigned)p0 < (unsigned)XROW_F)
            a = *reinterpret_cast<const float2*>(x + src0);
        if ((unsigned)p1 < (unsigned)XROW_F)
            c = *reinterpret_cast<const float2*>(x + src1);

        __stcs(reinterpret_cast<float4*>(out + fe),
               make_float4(a.x, a.y, c.x, c.y));
    }
}

extern "C" void kernel_launch(void* const* d_in, const int* in_sizes, int n_in,
                              void* d_out, int out_size)
{
    const float* x = (const float*)d_in[0];
    float* out = (float*)d_out;

    overlap_windows_kernel<<<NBLOCKS, NTHREADS>>>(x, out);
}

// round 12
// speedup vs baseline: 1.0523x; 1.0523x over previous
#include <cuda_runtime.h>

// CreateOverlappingWindows: x (B=64, T=2000, C=26) fp32 ->
// out (B*T, 19*26), N_CONTEXT=9, zero-padded edges.
//
// Champion config (R9): TILE_T=100, 512 threads, direct gather
// 2x LDG.64 -> STG.128 streaming (.cs), tile-local index math.
// This round: edge specialization — only tiles 0 and 19 need the
// zero-padding range checks; the 18 interior tiles run an unpredicated
// clone of the loop (pure loads, fewer ALU ops, loads batch earlier).
//
// src for flat tile offset fe: trow = fe/494, p = s0 + fe - trow*468,
// valid iff (unsigned)p < 52000 (edge tiles only).

#define B_DIM   64
#define T_DIM   2000
#define C_DIM   26
#define NCTX    9
#define WINDOW  19
#define ROW_F   (WINDOW * C_DIM)          // 494
#define SLIDE   (ROW_F - C_DIM)           // 468
#define XROW_F  (T_DIM * C_DIM)           // 52000 floats per batch
#define TILE_T  100                        // output rows per block
#define NTILES  (T_DIM / TILE_T)           // 20
#define TILE_F4 (TILE_T * ROW_F / 4)       // 12350 float4 per tile
#define NTHREADS 512

__global__ __launch_bounds__(NTHREADS) void overlap_windows_kernel(
    const float* __restrict__ x, float* __restrict__ out)
{
    const int tile = blockIdx.x;          // 0..19
    const int b    = blockIdx.y;          // 0..63
    const int t0   = tile * TILE_T;
    const int tid  = threadIdx.x;

    const float* xb = x + (size_t)b * XROW_F;
    float* tout = out + ((size_t)b * T_DIM + t0) * ROW_F;  // 16B aligned
    const int s0 = (t0 - NCTX) * C_DIM;   // negative only for tile 0

    if (tile != 0 && tile != NTILES - 1) {
        // ---- interior tiles (90% of work): no boundary checks ----
        #pragma unroll 4
        for (int i4 = tid; i4 < TILE_F4; i4 += NTHREADS) {
            const int fe = i4 * 4;

            const int trow0 = fe / ROW_F;                 // mul-hi divide
            const int k0    = fe - trow0 * ROW_F;         // 0..492, even
            const int p0    = s0 + fe - trow0 * SLIDE;
            const int trow1 = trow0 + ((k0 + 2 >= ROW_F) ? 1 : 0);
            const int p1    = s0 + (fe + 2) - trow1 * SLIDE;

            const float2 a = *reinterpret_cast<const float2*>(xb + p0);
            const float2 c = *reinterpret_cast<const float2*>(xb + p1);

            __stcs(reinterpret_cast<float4*>(tout + fe),
                   make_float4(a.x, a.y, c.x, c.y));
        }
    } else {
        // ---- edge tiles: predicated loads against [0, 52000) ----
        #pragma unroll 4
        for (int i4 = tid; i4 < TILE_F4; i4 += NTHREADS) {
            const int fe = i4 * 4;

            const int trow0 = fe / ROW_F;
            const int k0    = fe - trow0 * ROW_F;
            const int p0    = s0 + fe - trow0 * SLIDE;
            const int trow1 = trow0 + ((k0 + 2 >= ROW_F) ? 1 : 0);
            const int p1    = s0 + (fe + 2) - trow1 * SLIDE;

            float2 a = make_float2(0.0f, 0.0f);
            float2 c = make_float2(0.0f, 0.0f);
            if ((unsigned)p0 < (unsigned)XROW_F)
                a = *reinterpret_cast<const float2*>(xb + p0);
            if ((unsigned)p1 < (unsigned)XROW_F)
                c = *reinterpret_cast<const float2*>(xb + p1);

            __stcs(reinterpret_cast<float4*>(tout + fe),
                   make_float4(a.x, a.y, c.x, c.y));
        }
    }
}

extern "C" void kernel_launch(void* const* d_in, const int* in_sizes, int n_in,
                              void* d_out, int out_size)
{
    const float* x = (const float*)d_in[0];
    float* out = (float*)d_out;

    dim3 grid(NTILES, B_DIM);             // 20 x 64 = 1280 blocks
    overlap_windows_kernel<<<grid, NTHREADS>>>(x, out);
}